// round 2
// baseline (speedup 1.0000x reference)
#include <cuda_runtime.h>

#define NN 50000
#define EE 800000
#define E2 (EE + NN)
#define F0 256
#define FF 192
#define NH 3
#define HD 64
#define NC 40

// ---------------- static device scratch (no allocations allowed) ----------------
__device__ float    g_H[NN * FF];        // GEMM output of current layer (pre-aggregation features)
__device__ float    g_X[NN * FF];        // layer output (post aggregation+bias+relu)
__device__ float    g_asrc[NN * NH];
__device__ float    g_adst[NN * NH];
__device__ unsigned g_maxenc[NN * NH];   // order-preserving uint encoding of per-(dst,head) max
__device__ float    g_sum[NN * NH];
__device__ float    g_ee[E2 * NH];       // exp(logit - max) per edge per head
__device__ int      g_deg[NN];
__device__ int      g_cur[NN];
__device__ int      g_rowptr[NN + 1];
__device__ int      g_csrc[E2];          // CSR: src node of each incident edge
__device__ int      g_ceid[E2];          // CSR: edge id (into g_ee)

// ---------------- helpers ----------------
__device__ __forceinline__ unsigned enc_f(float f) {
    unsigned u = __float_as_uint(f);
    return (u & 0x80000000u) ? ~u : (u | 0x80000000u);
}
__device__ __forceinline__ float dec_f(unsigned u) {
    return __uint_as_float((u & 0x80000000u) ? (u ^ 0x80000000u) : ~u);
}

// ---------------- CSR build ----------------
__global__ void zero_nodes() {
    int i = blockIdx.x * blockDim.x + threadIdx.x;
    if (i < NN) { g_deg[i] = 0; g_cur[i] = 0; }
}

__global__ void hist_k(const int* __restrict__ dst) {
    int e = blockIdx.x * blockDim.x + threadIdx.x;
    if (e >= E2) return;
    int d = (e < EE) ? dst[e] : (e - EE);
    atomicAdd(&g_deg[d], 1);
}

__global__ void scan_k() {
    __shared__ int wsum[32];
    __shared__ int carry;
    int tid = threadIdx.x, lane = tid & 31, w = tid >> 5;
    if (tid == 0) { carry = 0; g_rowptr[0] = 0; }
    __syncthreads();
    const int TILES = (NN + 1023) / 1024;
    for (int t = 0; t < TILES; t++) {
        int i = t * 1024 + tid;
        int x = (i < NN) ? g_deg[i] : 0;
        #pragma unroll
        for (int o = 1; o < 32; o <<= 1) {
            int y = __shfl_up_sync(0xffffffffu, x, o);
            if (lane >= o) x += y;
        }
        if (lane == 31) wsum[w] = x;
        __syncthreads();
        if (w == 0) {
            int v = wsum[lane];
            #pragma unroll
            for (int o = 1; o < 32; o <<= 1) {
                int y = __shfl_up_sync(0xffffffffu, v, o);
                if (lane >= o) v += y;
            }
            wsum[lane] = v;
        }
        __syncthreads();
        int incl = x + ((w > 0) ? wsum[w - 1] : 0) + carry;
        if (i < NN) g_rowptr[i + 1] = incl;
        __syncthreads();
        if (tid == 1023) carry = incl;
        __syncthreads();
    }
}

__global__ void fill_k(const int* __restrict__ src, const int* __restrict__ dst) {
    int e = blockIdx.x * blockDim.x + threadIdx.x;
    if (e >= E2) return;
    int s, d;
    if (e < EE) { s = src[e]; d = dst[e]; } else { s = e - EE; d = s; }
    int pos = atomicAdd(&g_cur[d], 1);
    int at = g_rowptr[d] + pos;
    g_csrc[at] = s;
    g_ceid[at] = e;
}

// ---------------- SGEMM: C[M,Nd] = A[M,K] @ B[K,Nd] (+bias) ----------------
// BM=128 BN=64 BK=16, 256 threads, 8x4 micro-tile
__global__ void __launch_bounds__(256) sgemm_k(
    const float* __restrict__ A, const float* __restrict__ B, float* __restrict__ C,
    int M, int K, int Nd, const float* __restrict__ bias)
{
    __shared__ float As[16][128];
    __shared__ float Bs[16][64];
    int tid = threadIdx.x;
    int tx = tid & 15, ty = tid >> 4;
    int m0 = blockIdx.x * 128, n0 = blockIdx.y * 64;

    float acc[8][4];
    #pragma unroll
    for (int i = 0; i < 8; i++)
        #pragma unroll
        for (int j = 0; j < 4; j++) acc[i][j] = 0.f;

    for (int k0 = 0; k0 < K; k0 += 16) {
        // load A tile (128x16), store transposed As[k][m]
        #pragma unroll
        for (int i = 0; i < 2; i++) {
            int f = tid + i * 256;
            int r = f >> 2, c4 = f & 3;
            int row = m0 + r;
            float4 av = make_float4(0.f, 0.f, 0.f, 0.f);
            if (row < M) av = *(const float4*)&A[(long)row * K + k0 + c4 * 4];
            As[c4 * 4 + 0][r] = av.x;
            As[c4 * 4 + 1][r] = av.y;
            As[c4 * 4 + 2][r] = av.z;
            As[c4 * 4 + 3][r] = av.w;
        }
        // load B tile (16x64)
        {
            int rk = tid >> 4, c4 = tid & 15;
            int col = n0 + c4 * 4;
            float4 bv = make_float4(0.f, 0.f, 0.f, 0.f);
            if (col + 3 < Nd) {
                bv = *(const float4*)&B[(long)(k0 + rk) * Nd + col];
            } else {
                const float* bp = &B[(long)(k0 + rk) * Nd + col];
                if (col < Nd)     bv.x = bp[0];
                if (col + 1 < Nd) bv.y = bp[1];
                if (col + 2 < Nd) bv.z = bp[2];
            }
            *(float4*)&Bs[rk][c4 * 4] = bv;
        }
        __syncthreads();
        #pragma unroll
        for (int kk = 0; kk < 16; kk++) {
            float4 a0 = *(const float4*)&As[kk][ty * 8];
            float4 a1 = *(const float4*)&As[kk][ty * 8 + 4];
            float4 bf = *(const float4*)&Bs[kk][tx * 4];
            float ar[8] = {a0.x, a0.y, a0.z, a0.w, a1.x, a1.y, a1.z, a1.w};
            float br[4] = {bf.x, bf.y, bf.z, bf.w};
            #pragma unroll
            for (int i = 0; i < 8; i++)
                #pragma unroll
                for (int j = 0; j < 4; j++)
                    acc[i][j] += ar[i] * br[j];
        }
        __syncthreads();
    }
    #pragma unroll
    for (int i = 0; i < 8; i++) {
        int row = m0 + ty * 8 + i;
        if (row >= M) continue;
        #pragma unroll
        for (int j = 0; j < 4; j++) {
            int col = n0 + tx * 4 + j;
            if (col < Nd) {
                float v = acc[i][j];
                if (bias) v += bias[col];
                C[(long)row * Nd + col] = v;
            }
        }
    }
}

// ---------------- attention node terms (+ init of max/sum) ----------------
__global__ void attn_node_k(const float* __restrict__ att_s, const float* __restrict__ att_d) {
    int gw = (blockIdx.x * blockDim.x + threadIdx.x) >> 5;
    int lane = threadIdx.x & 31;
    if (gw >= NN * NH) return;
    int n = gw / NH, h = gw - n * NH;
    float2 hv = *(const float2*)&g_H[n * FF + h * HD + 2 * lane];
    float2 as = *(const float2*)&att_s[h * HD + 2 * lane];
    float2 ad = *(const float2*)&att_d[h * HD + 2 * lane];
    float ps = hv.x * as.x + hv.y * as.y;
    float pd = hv.x * ad.x + hv.y * ad.y;
    #pragma unroll
    for (int o = 16; o; o >>= 1) {
        ps += __shfl_xor_sync(0xffffffffu, ps, o);
        pd += __shfl_xor_sync(0xffffffffu, pd, o);
    }
    if (lane == 0) {
        g_asrc[gw] = ps;
        g_adst[gw] = pd;
        g_maxenc[gw] = 0u;   // smallest possible encoded value
        g_sum[gw] = 0.f;
    }
}

// ---------------- edge pass 1: segment max ----------------
__global__ void edge_max_k(const int* __restrict__ src, const int* __restrict__ dst) {
    int e = blockIdx.x * blockDim.x + threadIdx.x;
    if (e >= E2) return;
    int s, d;
    if (e < EE) { s = src[e]; d = dst[e]; } else { s = e - EE; d = s; }
    #pragma unroll
    for (int h = 0; h < NH; h++) {
        float l = g_asrc[s * NH + h] + g_adst[d * NH + h];
        l = (l > 0.f) ? l : 0.2f * l;
        atomicMax(&g_maxenc[d * NH + h], enc_f(l));
    }
}

// ---------------- edge pass 2: exp + segment sum ----------------
__global__ void edge_exp_k(const int* __restrict__ src, const int* __restrict__ dst) {
    int e = blockIdx.x * blockDim.x + threadIdx.x;
    if (e >= E2) return;
    int s, d;
    if (e < EE) { s = src[e]; d = dst[e]; } else { s = e - EE; d = s; }
    #pragma unroll
    for (int h = 0; h < NH; h++) {
        float l = g_asrc[s * NH + h] + g_adst[d * NH + h];
        l = (l > 0.f) ? l : 0.2f * l;
        float m = dec_f(g_maxenc[d * NH + h]);
        float ev = __expf(l - m);
        g_ee[e * NH + h] = ev;
        atomicAdd(&g_sum[d * NH + h], ev);
    }
}

// ---------------- aggregation: gather via CSR, one warp per (node,head) ----------------
__global__ void aggregate_k(const float* __restrict__ bias, float* __restrict__ out, int do_relu) {
    int gw = (blockIdx.x * blockDim.x + threadIdx.x) >> 5;
    int lane = threadIdx.x & 31;
    if (gw >= NN * NH) return;
    int n = gw / NH, h = gw - n * NH;
    int beg = g_rowptr[n], end = g_rowptr[n + 1];
    float inv = 1.0f / g_sum[gw];
    int col = h * HD + 2 * lane;
    float ax = 0.f, ay = 0.f;
    for (int base = beg; base < end; base += 32) {
        int idx = base + lane;
        int s = 0; float ev = 0.f;
        if (idx < end) {
            s = g_csrc[idx];
            ev = g_ee[g_ceid[idx] * NH + h];
        }
        int cnt = min(32, end - base);
        for (int j = 0; j < cnt; j++) {
            int sj   = __shfl_sync(0xffffffffu, s, j);
            float ej = __shfl_sync(0xffffffffu, ev, j);
            float2 v = *(const float2*)&g_H[sj * FF + col];
            ax += ej * v.x;
            ay += ej * v.y;
        }
    }
    ax = ax * inv + bias[col];
    ay = ay * inv + bias[col + 1];
    if (do_relu) { ax = fmaxf(ax, 0.f); ay = fmaxf(ay, 0.f); }
    *(float2*)&out[n * FF + col] = make_float2(ax, ay);
}

// ---------------- launcher ----------------
extern "C" void kernel_launch(void* const* d_in, const int* in_sizes, int n_in,
                              void* d_out, int out_size)
{
    const float* x    = (const float*)d_in[0];
    const int*   ei   = (const int*)  d_in[1];
    const float* W1   = (const float*)d_in[2];
    const float* as1  = (const float*)d_in[3];
    const float* ad1  = (const float*)d_in[4];
    const float* b1   = (const float*)d_in[5];
    const float* W2   = (const float*)d_in[6];
    const float* as2  = (const float*)d_in[7];
    const float* ad2  = (const float*)d_in[8];
    const float* b2   = (const float*)d_in[9];
    const float* Wout = (const float*)d_in[10];
    const float* bout = (const float*)d_in[11];
    float* out = (float*)d_out;

    const int* src = ei;
    const int* dst = ei + EE;

    void* p;
    cudaGetSymbolAddress(&p, g_H); float* pH = (float*)p;
    cudaGetSymbolAddress(&p, g_X); float* pX = (float*)p;

    const int EB = (E2 + 255) / 256;
    const int NB = (NN + 255) / 256;
    const int WB = (NN * NH * 32 + 255) / 256;   // one warp per (node, head)

    // CSR build (shared by both layers)
    zero_nodes<<<NB, 256>>>();
    hist_k<<<EB, 256>>>(dst);
    scan_k<<<1, 1024>>>();
    fill_k<<<EB, 256>>>(src, dst);

    // ---- layer 1 ----
    sgemm_k<<<dim3((NN + 127) / 128, (FF + 63) / 64), 256>>>(x, W1, pH, NN, F0, FF, nullptr);
    attn_node_k<<<WB, 256>>>(as1, ad1);
    edge_max_k<<<EB, 256>>>(src, dst);
    edge_exp_k<<<EB, 256>>>(src, dst);
    aggregate_k<<<WB, 256>>>(b1, pX, 1);

    // ---- layer 2 ----
    sgemm_k<<<dim3((NN + 127) / 128, (FF + 63) / 64), 256>>>(pX, W2, pH, NN, FF, FF, nullptr);
    attn_node_k<<<WB, 256>>>(as2, ad2);
    edge_max_k<<<EB, 256>>>(src, dst);
    edge_exp_k<<<EB, 256>>>(src, dst);
    aggregate_k<<<WB, 256>>>(b2, pX, 1);

    // ---- readout ----
    sgemm_k<<<dim3((NN + 127) / 128, (NC + 63) / 64), 256>>>(pX, Wout, out, NN, FF, NC, bout);
}

// round 6
// speedup vs baseline: 2.0068x; 2.0068x over previous
#include <cuda_runtime.h>
#include <cstdint>

#define NN 50000
#define EE 800000
#define E2 (EE + NN)
#define F0 256
#define FF 192
#define NH 3
#define HD 64
#define NC 40

// ---------------- static device scratch ----------------
__device__ __align__(128) float    g_H[NN * FF];
__device__ __align__(128) float    g_X[NN * FF];
__device__ float    g_asrc[NN * NH];
__device__ float    g_adst[NN * NH];
__device__ unsigned g_maxenc[NN * NH];
__device__ float    g_sum[NN * NH];
__device__ __align__(128) float    g_ee[E2 * NH];
__device__ int      g_deg[NN];
__device__ int      g_cur[NN];
__device__ int      g_rowptr[NN + 1];
__device__ int      g_csrc[E2];
__device__ int      g_ceid[E2];

// ---------------- helpers ----------------
__device__ __forceinline__ unsigned enc_f(float f) {
    unsigned u = __float_as_uint(f);
    return (u & 0x80000000u) ? ~u : (u | 0x80000000u);
}
__device__ __forceinline__ float dec_f(unsigned u) {
    return __uint_as_float((u & 0x80000000u) ? (u ^ 0x80000000u) : ~u);
}
__device__ __forceinline__ uint32_t s2u(const void* p) {
    uint32_t a;
    asm("{ .reg .u64 t; cvta.to.shared.u64 t, %1; cvt.u32.u64 %0, t; }" : "=r"(a) : "l"(p));
    return a;
}
__device__ __forceinline__ void cp16(uint32_t s, const void* g) {
    asm volatile("cp.async.cg.shared.global [%0], [%1], 16;" :: "r"(s), "l"(g));
}
__device__ __forceinline__ void cp16z(uint32_t s, const void* g, int valid) {
    asm volatile("cp.async.cg.shared.global [%0], [%1], 16, %2;" :: "r"(s), "l"(g), "r"(valid));
}
__device__ __forceinline__ void cp_commit() { asm volatile("cp.async.commit_group;" ::: "memory"); }
template<int NPEND> __device__ __forceinline__ void cp_wait() {
    asm volatile("cp.async.wait_group %0;" :: "n"(NPEND) : "memory");
}
__device__ __forceinline__ uint32_t f2tf(float f) {
    uint32_t r;
    asm("cvt.rna.tf32.f32 %0, %1;" : "=r"(r) : "f"(f));
    return r;
}
__device__ __forceinline__ void mma_tf32(float* c, const uint32_t* a, const uint32_t* b) {
    asm volatile(
        "mma.sync.aligned.m16n8k8.row.col.f32.tf32.tf32.f32 "
        "{%0,%1,%2,%3}, {%4,%5,%6,%7}, {%8,%9}, {%0,%1,%2,%3};"
        : "+f"(c[0]), "+f"(c[1]), "+f"(c[2]), "+f"(c[3])
        : "r"(a[0]), "r"(a[1]), "r"(a[2]), "r"(a[3]), "r"(b[0]), "r"(b[1]));
}

// ---------------- tf32 mma.sync GEMM: C[M,N] = A[M,K] @ B[K,N] (+bias) ----------------
// BM=128 BN=64 BK=16, 256 threads = 8 warps (4 along M x 2 along N), warp tile 32x32.
#define AST 20   // As row stride (floats): 128 rows x [k 0..15]
#define BST 72   // Bs row stride (floats): 16 k-rows x [n 0..63]

__global__ void __launch_bounds__(256) gemm_mma_k(
    const float* __restrict__ A, const float* __restrict__ B, float* __restrict__ C,
    int M, int K, int N, const float* __restrict__ bias)
{
    __shared__ float As[2][128 * AST];
    __shared__ float Bs[2][16 * BST];

    int tid = threadIdx.x, wid = tid >> 5, lane = tid & 31;
    int warp_m = wid & 3, warp_n = wid >> 2;
    int m0 = blockIdx.x * 128, n0 = blockIdx.y * 64;
    int gid = lane >> 2, tig = lane & 3;   // groupID, thread-in-group

    float acc[2][4][4];
    #pragma unroll
    for (int i = 0; i < 2; i++)
        #pragma unroll
        for (int j = 0; j < 4; j++)
            #pragma unroll
            for (int t = 0; t < 4; t++) acc[i][j][t] = 0.f;

    uint32_t asb[2] = { s2u(As[0]), s2u(As[1]) };
    uint32_t bsb[2] = { s2u(Bs[0]), s2u(Bs[1]) };

    // ---- tile prefetch ----
    auto prefetch = [&](int st, int kt) {
        int k0 = kt * 16;
        // A tile: 128 rows x 16 cols, [m][k] layout. 512 16B-chunks / 256 thr = 2 each.
        #pragma unroll
        for (int i = 0; i < 2; i++) {
            int idx = tid + i * 256;
            int m = idx >> 2, ch = idx & 3;
            int grow = m0 + m; if (grow >= M) grow = M - 1;
            cp16(asb[st] + (uint32_t)(m * AST + ch * 4) * 4u,
                 A + (size_t)grow * K + k0 + ch * 4);
        }
        // B tile: 16 k-rows x 64 cols, [k][n] layout. 256 chunks / 256 thr = 1 each.
        {
            int k = tid >> 4, ch = tid & 15;
            int col = n0 + ch * 4;
            int valid = (N - col) * 4;
            if (valid > 16) valid = 16;
            if (valid < 0) valid = 0;
            const float* src = B + (size_t)(k0 + k) * N + (valid > 0 ? col : 0);
            cp16z(bsb[st] + (uint32_t)(k * BST + ch * 4) * 4u, src, valid);
        }
    };

    int KT = K >> 4;
    prefetch(0, 0); cp_commit();
    prefetch(1, 1); cp_commit();

    for (int kt = 0; kt < KT; kt++) {
        int st = kt & 1;
        if (kt + 1 < KT) cp_wait<1>(); else cp_wait<0>();
        __syncthreads();

        const float* as = As[st];
        const float* bs = Bs[st];
        #pragma unroll
        for (int ks = 0; ks < 2; ks++) {
            int kk = ks * 8;
            uint32_t af[2][4], bf[4][2];
            #pragma unroll
            for (int mt = 0; mt < 2; mt++) {
                int r = warp_m * 32 + mt * 16 + gid;
                af[mt][0] = f2tf(as[r * AST + kk + tig]);
                af[mt][1] = f2tf(as[(r + 8) * AST + kk + tig]);
                af[mt][2] = f2tf(as[r * AST + kk + tig + 4]);
                af[mt][3] = f2tf(as[(r + 8) * AST + kk + tig + 4]);
            }
            #pragma unroll
            for (int nt = 0; nt < 4; nt++) {
                int c = warp_n * 32 + nt * 8 + gid;
                bf[nt][0] = f2tf(bs[(kk + tig) * BST + c]);
                bf[nt][1] = f2tf(bs[(kk + tig + 4) * BST + c]);
            }
            #pragma unroll
            for (int mt = 0; mt < 2; mt++)
                #pragma unroll
                for (int nt = 0; nt < 4; nt++)
                    mma_tf32(acc[mt][nt], af[mt], bf[nt]);
        }
        __syncthreads();
        if (kt + 2 < KT) { prefetch(st, kt + 2); cp_commit(); }
    }

    // ---- epilogue ----
    #pragma unroll
    for (int mt = 0; mt < 2; mt++) {
        #pragma unroll
        for (int nt = 0; nt < 4; nt++) {
            int col = n0 + warp_n * 32 + nt * 8 + tig * 2;
            if (col >= N) continue;
            float bx = 0.f, by = 0.f;
            if (bias) { bx = bias[col]; by = bias[col + 1]; }
            int r0 = m0 + warp_m * 32 + mt * 16 + gid;
            if (r0 < M)
                *(float2*)&C[(size_t)r0 * N + col] =
                    make_float2(acc[mt][nt][0] + bx, acc[mt][nt][1] + by);
            int r1 = r0 + 8;
            if (r1 < M)
                *(float2*)&C[(size_t)r1 * N + col] =
                    make_float2(acc[mt][nt][2] + bx, acc[mt][nt][3] + by);
        }
    }
}

// ---------------- CSR build ----------------
__global__ void zero_nodes() {
    int i = blockIdx.x * blockDim.x + threadIdx.x;
    if (i < NN) { g_deg[i] = 0; g_cur[i] = 0; }
}

__global__ void hist_k(const int* __restrict__ dst) {
    int e = blockIdx.x * blockDim.x + threadIdx.x;
    if (e >= E2) return;
    int d = (e < EE) ? dst[e] : (e - EE);
    atomicAdd(&g_deg[d], 1);
}

__global__ void scan_k() {
    __shared__ int wsum[32];
    __shared__ int carry;
    int tid = threadIdx.x, lane = tid & 31, w = tid >> 5;
    if (tid == 0) { carry = 0; g_rowptr[0] = 0; }
    __syncthreads();
    const int TILES = (NN + 1023) / 1024;
    for (int t = 0; t < TILES; t++) {
        int i = t * 1024 + tid;
        int x = (i < NN) ? g_deg[i] : 0;
        #pragma unroll
        for (int o = 1; o < 32; o <<= 1) {
            int y = __shfl_up_sync(0xffffffffu, x, o);
            if (lane >= o) x += y;
        }
        if (lane == 31) wsum[w] = x;
        __syncthreads();
        if (w == 0) {
            int v = wsum[lane];
            #pragma unroll
            for (int o = 1; o < 32; o <<= 1) {
                int y = __shfl_up_sync(0xffffffffu, v, o);
                if (lane >= o) v += y;
            }
            wsum[lane] = v;
        }
        __syncthreads();
        int incl = x + ((w > 0) ? wsum[w - 1] : 0) + carry;
        if (i < NN) g_rowptr[i + 1] = incl;
        __syncthreads();
        if (tid == 1023) carry = incl;
        __syncthreads();
    }
}

__global__ void fill_k(const int* __restrict__ src, const int* __restrict__ dst) {
    int e = blockIdx.x * blockDim.x + threadIdx.x;
    if (e >= E2) return;
    int s, d;
    if (e < EE) { s = src[e]; d = dst[e]; } else { s = e - EE; d = s; }
    int pos = atomicAdd(&g_cur[d], 1);
    int at = g_rowptr[d] + pos;
    g_csrc[at] = s;
    g_ceid[at] = e;
}

// ---------------- attention node terms (+ init of max/sum) ----------------
__global__ void attn_node_k(const float* __restrict__ att_s, const float* __restrict__ att_d) {
    int gw = (blockIdx.x * blockDim.x + threadIdx.x) >> 5;
    int lane = threadIdx.x & 31;
    if (gw >= NN * NH) return;
    int n = gw / NH, h = gw - n * NH;
    float2 hv = *(const float2*)&g_H[n * FF + h * HD + 2 * lane];
    float2 as = *(const float2*)&att_s[h * HD + 2 * lane];
    float2 ad = *(const float2*)&att_d[h * HD + 2 * lane];
    float ps = hv.x * as.x + hv.y * as.y;
    float pd = hv.x * ad.x + hv.y * ad.y;
    #pragma unroll
    for (int o = 16; o; o >>= 1) {
        ps += __shfl_xor_sync(0xffffffffu, ps, o);
        pd += __shfl_xor_sync(0xffffffffu, pd, o);
    }
    if (lane == 0) {
        g_asrc[gw] = ps;
        g_adst[gw] = pd;
        g_maxenc[gw] = 0u;
        g_sum[gw] = 0.f;
    }
}

// ---------------- edge pass 1: segment max ----------------
__global__ void edge_max_k(const int* __restrict__ src, const int* __restrict__ dst) {
    int e = blockIdx.x * blockDim.x + threadIdx.x;
    if (e >= E2) return;
    int s, d;
    if (e < EE) { s = src[e]; d = dst[e]; } else { s = e - EE; d = s; }
    #pragma unroll
    for (int h = 0; h < NH; h++) {
        float l = g_asrc[s * NH + h] + g_adst[d * NH + h];
        l = (l > 0.f) ? l : 0.2f * l;
        atomicMax(&g_maxenc[d * NH + h], enc_f(l));
    }
}

// ---------------- edge pass 2: exp + segment sum ----------------
__global__ void edge_exp_k(const int* __restrict__ src, const int* __restrict__ dst) {
    int e = blockIdx.x * blockDim.x + threadIdx.x;
    if (e >= E2) return;
    int s, d;
    if (e < EE) { s = src[e]; d = dst[e]; } else { s = e - EE; d = s; }
    #pragma unroll
    for (int h = 0; h < NH; h++) {
        float l = g_asrc[s * NH + h] + g_adst[d * NH + h];
        l = (l > 0.f) ? l : 0.2f * l;
        float m = dec_f(g_maxenc[d * NH + h]);
        float ev = __expf(l - m);
        g_ee[e * NH + h] = ev;
        atomicAdd(&g_sum[d * NH + h], ev);
    }
}

// ---------------- aggregation: gather via CSR, one warp per (node,head) ----------------
__global__ void aggregate_k(const float* __restrict__ bias, float* __restrict__ out, int do_relu) {
    int gw = (blockIdx.x * blockDim.x + threadIdx.x) >> 5;
    int lane = threadIdx.x & 31;
    if (gw >= NN * NH) return;
    int n = gw / NH, h = gw - n * NH;
    int beg = g_rowptr[n], end = g_rowptr[n + 1];
    float inv = 1.0f / g_sum[gw];
    int col = h * HD + 2 * lane;
    float ax = 0.f, ay = 0.f;
    for (int base = beg; base < end; base += 32) {
        int idx = base + lane;
        int s = 0; float ev = 0.f;
        if (idx < end) {
            s = g_csrc[idx];
            ev = g_ee[g_ceid[idx] * NH + h];
        }
        int cnt = min(32, end - base);
        for (int j = 0; j < cnt; j++) {
            int sj   = __shfl_sync(0xffffffffu, s, j);
            float ej = __shfl_sync(0xffffffffu, ev, j);
            float2 v = *(const float2*)&g_H[sj * FF + col];
            ax += ej * v.x;
            ay += ej * v.y;
        }
    }
    ax = ax * inv + bias[col];
    ay = ay * inv + bias[col + 1];
    if (do_relu) { ax = fmaxf(ax, 0.f); ay = fmaxf(ay, 0.f); }
    *(float2*)&out[n * FF + col] = make_float2(ax, ay);
}

// ---------------- launcher ----------------
extern "C" void kernel_launch(void* const* d_in, const int* in_sizes, int n_in,
                              void* d_out, int out_size)
{
    const float* x    = (const float*)d_in[0];
    const int*   ei   = (const int*)  d_in[1];
    const float* W1   = (const float*)d_in[2];
    const float* as1  = (const float*)d_in[3];
    const float* ad1  = (const float*)d_in[4];
    const float* b1   = (const float*)d_in[5];
    const float* W2   = (const float*)d_in[6];
    const float* as2  = (const float*)d_in[7];
    const float* ad2  = (const float*)d_in[8];
    const float* b2   = (const float*)d_in[9];
    const float* Wout = (const float*)d_in[10];
    const float* bout = (const float*)d_in[11];
    float* out = (float*)d_out;

    const int* src = ei;
    const int* dst = ei + EE;

    void* p;
    cudaGetSymbolAddress(&p, g_H); float* pH = (float*)p;
    cudaGetSymbolAddress(&p, g_X); float* pX = (float*)p;

    const int EB = (E2 + 255) / 256;
    const int NB = (NN + 255) / 256;
    const int WB = (NN * NH * 32 + 255) / 256;
    const int GB = (NN + 127) / 128;

    // CSR build (shared by both layers)
    zero_nodes<<<NB, 256>>>();
    hist_k<<<EB, 256>>>(dst);
    scan_k<<<1, 1024>>>();
    fill_k<<<EB, 256>>>(src, dst);

    // ---- layer 1 ----
    gemm_mma_k<<<dim3(GB, (FF + 63) / 64), 256>>>(x, W1, pH, NN, F0, FF, nullptr);
    attn_node_k<<<WB, 256>>>(as1, ad1);
    edge_max_k<<<EB, 256>>>(src, dst);
    edge_exp_k<<<EB, 256>>>(src, dst);
    aggregate_k<<<WB, 256>>>(b1, pX, 1);

    // ---- layer 2 ----
    gemm_mma_k<<<dim3(GB, (FF + 63) / 64), 256>>>(pX, W2, pH, NN, FF, FF, nullptr);
    attn_node_k<<<WB, 256>>>(as2, ad2);
    edge_max_k<<<EB, 256>>>(src, dst);
    edge_exp_k<<<EB, 256>>>(src, dst);
    aggregate_k<<<WB, 256>>>(b2, pX, 1);

    // ---- readout ----
    gemm_mma_k<<<dim3(GB, 1), 256>>>(pX, Wout, out, NN, FF, NC, bout);
}